// round 15
// baseline (speedup 1.0000x reference)
#include <cuda_runtime.h>
#include <cuda_fp16.h>
#include <cstdint>

// SimpleGAT reduces exactly to out = inputs @ W (softmax over a broadcast-
// constant axis is uniform; the einsum multiplies H by sum_k(alpha)==1).
// fp32 GEMM M=131072, N=256, K=256 via mma.sync fp16 (base sm_103 target).
// Pure fp16 single-term scheme (calibrated rel_err 2.94e-4 vs 1e-3 gate).
// R14: KC 32->64, 2-stage pipeline: 4 sync points instead of 8. The profile
//      across R9-R13 shows lockstep barrier storms (all warps burst MIO after
//      each barrier), not cp.async waits, as the binder. Doubling the free-
//      run span halves the storm frequency.

namespace cfg {
constexpr int KDIM = 256, NDIM = 256;
constexpr int BM = 128, BN = 128, KC = 64;
constexpr int NT = 256;                          // 8 warps
constexpr int NCHUNK = KDIM / KC;                // 4
constexpr int A_STRIDE_B = 288;                  // 72 floats: conflict-free LDS.64
constexpr uint32_t A_STAGE = 128u * A_STRIDE_B;  // 36864 B, 2 stages
constexpr int W_STRIDE_B = 144;                  // 64 fp16 + 16B pad: conflict-free LDSM
constexpr uint32_t W_STAGE = 128u * W_STRIDE_B;  // 18432 B, 2 stages
constexpr uint32_t OFF_A = 0;
constexpr uint32_t OFF_W = 2 * A_STAGE;          // 73728
constexpr uint32_t SMEM_TOTAL = OFF_W + 2 * W_STAGE;  // 110592 -> 2 CTAs/SM
}  // namespace cfg

// W transposed to fp16 [n][k].
__device__ __half g_Wh[cfg::NDIM * cfg::KDIM];

// ---------------- helpers ----------------
__device__ __forceinline__ uint32_t smem_u32(const void* p) {
    uint32_t a;
    asm("{ .reg .u64 t; cvta.to.shared.u64 t, %1; cvt.u32.u64 %0, t; }" : "=r"(a) : "l"(p));
    return a;
}
__device__ __forceinline__ void cp_async16(uint32_t dst, const void* src) {
    asm volatile("cp.async.cg.shared.global [%0], [%1], 16;" :: "r"(dst), "l"(src));
}
__device__ __forceinline__ void cp_commit() { asm volatile("cp.async.commit_group;"); }
template <int N>
__device__ __forceinline__ void cp_wait() {
    asm volatile("cp.async.wait_group %0;" :: "n"(N) : "memory");
}
__device__ __forceinline__ void ldsm_x4(uint32_t* r, uint32_t addr) {
    asm volatile("ldmatrix.sync.aligned.m8n8.x4.shared.b16 {%0,%1,%2,%3}, [%4];"
                 : "=r"(r[0]), "=r"(r[1]), "=r"(r[2]), "=r"(r[3]) : "r"(addr));
}
__device__ __forceinline__ float2 lds64(uint32_t addr) {
    float2 v;
    asm volatile("ld.shared.v2.f32 {%0,%1}, [%2];" : "=f"(v.x), "=f"(v.y) : "r"(addr));
    return v;
}
__device__ __forceinline__ void mma_f16(float* c, const uint32_t* a, const uint32_t* b) {
    asm volatile(
        "mma.sync.aligned.m16n8k16.row.col.f32.f16.f16.f32 "
        "{%0,%1,%2,%3}, {%4,%5,%6,%7}, {%8,%9}, {%0,%1,%2,%3};"
        : "+f"(c[0]), "+f"(c[1]), "+f"(c[2]), "+f"(c[3])
        : "r"(a[0]), "r"(a[1]), "r"(a[2]), "r"(a[3]), "r"(b[0]), "r"(b[1]));
}
// pack two fp32 -> one fp16x2 (lo = x, hi = y), round-to-nearest
__device__ __forceinline__ uint32_t cvt_f16x2(float2 v) {
    uint32_t r;
    asm("cvt.rn.f16x2.f32 %0, %1, %2;" : "=r"(r) : "f"(v.y), "f"(v.x));
    return r;
}

// ---------------- kernels ----------------

__global__ void gat_prep_w(const float* __restrict__ W) {
    using namespace cfg;
    int idx = blockIdx.x * blockDim.x + threadIdx.x;  // 65536
    int k = idx >> 8, n = idx & 255;
    g_Wh[n * KDIM + k] = __float2half_rn(W[idx]);
}

__global__ __launch_bounds__(cfg::NT, 2)
void gat_mma_gemm(const float* __restrict__ A, float* __restrict__ C) {
    using namespace cfg;
    extern __shared__ char smem[];
    const uint32_t sb = smem_u32(smem);

    const int tid = threadIdx.x;
    const int wid = tid >> 5, lane = tid & 31;   // warp owns rows wid*16..+15, all 128 cols
    const size_t rowBase = (size_t)blockIdx.y * BM;
    const int colBase = blockIdx.x * BN;

    // A cp.async: 128 rows x 16 segs(16B) = 2048 segs, 8 per thread
    const int cpRow = tid >> 3;                // +32*i, i<4
    const int cpSeg = (tid & 7) * 2;           // 2 consecutive segs per row
    // W cp.async: 128 rows x 8 segs = 1024 segs, 4 per thread
    const int wRowLd = tid >> 1;               // 0..127
    const int wSegLd = (tid & 1) * 4;          // 4 consecutive segs

    auto cp_A = [&](int c) {           // one commit group
        const uint32_t base = sb + OFF_A + (uint32_t)(c & 1) * A_STAGE;
        const float* src = A + (rowBase + cpRow) * KDIM + c * KC + cpSeg * 4;
#pragma unroll
        for (int i = 0; i < 4; i++) {
            const uint32_t d = base + (uint32_t)(cpRow + i * 32) * A_STRIDE_B + cpSeg * 16;
            const float* s = src + (size_t)i * 32 * KDIM;
            cp_async16(d, s);
            cp_async16(d + 16, s + 4);
        }
        cp_commit();
    };
    auto cp_W = [&](int c) {           // one commit group
        const uint32_t base = sb + OFF_W + (uint32_t)(c & 1) * W_STAGE
                            + (uint32_t)wRowLd * W_STRIDE_B;
        const __half* src = g_Wh + (size_t)(colBase + wRowLd) * KDIM + c * KC;
#pragma unroll
        for (int i = 0; i < 4; i++)
            cp_async16(base + (wSegLd + i) * 16, src + (wSegLd + i) * 8);
        cp_commit();
    };

    // prologue: force chunk 0
    cp_A(0); cp_W(0);
    cp_wait<0>();
    __syncthreads();

    // per-lane fragment address components
    const uint32_t aOff = (uint32_t)(wid * 16 + (lane >> 2)) * A_STRIDE_B + (lane & 3) * 8;
    const uint32_t wRow = (uint32_t)(lane & 15);
    const uint32_t wKo = (uint32_t)((lane >> 4) << 3);  // elems

    float acc[16][4];
#pragma unroll
    for (int n = 0; n < 16; n++)
#pragma unroll
        for (int q = 0; q < 4; q++) acc[n][q] = 0.0f;

#pragma unroll 1
    for (int c = 0; c < NCHUNK; c++) {
        // depth-1 prefetch into the other stage; a full (double-length) chunk
        // of compute covers its landing time.
        if (c + 1 < NCHUNK) { cp_A(c + 1); cp_W(c + 1); }

        const uint32_t aBase = sb + OFF_A + (uint32_t)(c & 1) * A_STAGE + aOff;
        const uint32_t wBase = sb + OFF_W + (uint32_t)(c & 1) * W_STAGE;

#pragma unroll
        for (int s = 0; s < 4; s++) {           // 4 k-steps of 16
            // --- A fragment (16x16): 4 x LDS.64 + 4 x cvt ---
            uint32_t aF[4];
            {
                const uint32_t b0 = aBase + (uint32_t)s * 64;
                aF[0] = cvt_f16x2(lds64(b0));
                aF[1] = cvt_f16x2(lds64(b0 + 8 * A_STRIDE_B));
                aF[2] = cvt_f16x2(lds64(b0 + 32));
                aF[3] = cvt_f16x2(lds64(b0 + 8 * A_STRIDE_B + 32));
            }
            const uint32_t kcol = (uint32_t)(s * 16) + wKo;
            // 16 n-tiles in two halves (caps live B regs at 16)
#pragma unroll
            for (int h = 0; h < 2; h++) {
                const uint32_t rowOff = (wRow + (uint32_t)h * 64) * W_STRIDE_B;
                uint32_t bF[8][2];
#pragma unroll
                for (int p = 0; p < 4; p++) {
                    uint32_t r[4];
                    ldsm_x4(r, wBase + rowOff + p * 16 * W_STRIDE_B + kcol * 2);
                    bF[2 * p][0] = r[0]; bF[2 * p][1] = r[2];
                    bF[2 * p + 1][0] = r[1]; bF[2 * p + 1][1] = r[3];
                }
#pragma unroll
                for (int n = 0; n < 8; n++) mma_f16(acc[h * 8 + n], aF, bF[n]);
            }
        }

        if (c + 1 < NCHUNK) {
            cp_wait<0>();          // both groups for chunk c+1 landed
            __syncthreads();
        }
    }

    // ---- epilogue: warp wid -> rows wid*16..+15, cols 0..127 ----
    const int g = lane >> 2, tg = lane & 3;
    const size_t m0 = rowBase + wid * 16 + g;
#pragma unroll
    for (int n = 0; n < 16; n++) {
        const int col = colBase + n * 8 + tg * 2;
        *reinterpret_cast<float2*>(C + m0 * NDIM + col) =
            make_float2(acc[n][0], acc[n][1]);
        *reinterpret_cast<float2*>(C + (m0 + 8) * NDIM + col) =
            make_float2(acc[n][2], acc[n][3]);
    }
}

extern "C" void kernel_launch(void* const* d_in, const int* in_sizes, int n_in,
                              void* d_out, int out_size) {
    using namespace cfg;
    const float* A = (const float*)d_in[0];   // inputs [B,T,K] -> [M, 256]
    const float* W = (const float*)d_in[1];   // W [256, 256]
    float* C = (float*)d_out;

    const int M = in_sizes[0] / KDIM;         // 131072

    cudaFuncSetAttribute(gat_mma_gemm, cudaFuncAttributeMaxDynamicSharedMemorySize, SMEM_TOTAL);

    gat_prep_w<<<(KDIM * NDIM) / 256, 256>>>(W);
    dim3 grid(NDIM / BN, M / BM);
    gat_mma_gemm<<<grid, NT, SMEM_TOTAL>>>(A, C);
}

// round 16
// speedup vs baseline: 1.1682x; 1.1682x over previous
#include <cuda_runtime.h>
#include <cuda_fp16.h>
#include <cstdint>

// SimpleGAT reduces exactly to out = inputs @ W (softmax over a broadcast-
// constant axis is uniform; the einsum multiplies H by sum_k(alpha)==1).
// fp32 GEMM M=131072, N=256, K=256 via mma.sync fp16 (base sm_103 target).
// Pure fp16 single-term scheme (calibrated rel_err 2.94e-4 vs 1e-3 gate).
// R15: R9 champion + 4x2 warp layout (warp tile 32x64). W LDSM redundancy
//      8x -> 4x: per-chunk smem reads 80KB -> 64KB. Everything else (3-stage
//      A/W cp.async, depth-2 prefetch, wait<2> never draining, one sync per
//      chunk) is byte-identical to R9. (R10-R14 structural variants all
//      regressed; this is the one identified waste in the champion.)

namespace cfg {
constexpr int KDIM = 256, NDIM = 256;
constexpr int BM = 128, BN = 128, KC = 32;
constexpr int NT = 256;                         // 8 warps (4 M x 2 N)
constexpr int NCHUNK = KDIM / KC;               // 8
constexpr int A_STRIDE_B = 160;                 // 40 floats: conflict-free LDS.64
constexpr uint32_t A_STAGE = 128u * A_STRIDE_B; // 20480 B, 3 stages
constexpr int W_STRIDE_B = 80;                  // 32 fp16 + 16B pad: conflict-free LDSM
constexpr uint32_t W_STAGE = 128u * W_STRIDE_B; // 10240 B, 3 stages
constexpr uint32_t OFF_A = 0;
constexpr uint32_t OFF_W = 3 * A_STAGE;         // 61440
constexpr uint32_t SMEM_TOTAL = OFF_W + 3 * W_STAGE;  // 92160 -> 2 CTAs/SM
}  // namespace cfg

// W transposed to fp16 [n][k].
__device__ __half g_Wh[cfg::NDIM * cfg::KDIM];

// ---------------- helpers ----------------
__device__ __forceinline__ uint32_t smem_u32(const void* p) {
    uint32_t a;
    asm("{ .reg .u64 t; cvta.to.shared.u64 t, %1; cvt.u32.u64 %0, t; }" : "=r"(a) : "l"(p));
    return a;
}
__device__ __forceinline__ void cp_async16(uint32_t dst, const void* src) {
    asm volatile("cp.async.cg.shared.global [%0], [%1], 16;" :: "r"(dst), "l"(src));
}
__device__ __forceinline__ void cp_commit() { asm volatile("cp.async.commit_group;"); }
template <int N>
__device__ __forceinline__ void cp_wait() {
    asm volatile("cp.async.wait_group %0;" :: "n"(N) : "memory");
}
__device__ __forceinline__ void ldsm_x4(uint32_t* r, uint32_t addr) {
    asm volatile("ldmatrix.sync.aligned.m8n8.x4.shared.b16 {%0,%1,%2,%3}, [%4];"
                 : "=r"(r[0]), "=r"(r[1]), "=r"(r[2]), "=r"(r[3]) : "r"(addr));
}
__device__ __forceinline__ float2 lds64(uint32_t addr) {
    float2 v;
    asm volatile("ld.shared.v2.f32 {%0,%1}, [%2];" : "=f"(v.x), "=f"(v.y) : "r"(addr));
    return v;
}
__device__ __forceinline__ void mma_f16(float* c, const uint32_t* a, const uint32_t* b) {
    asm volatile(
        "mma.sync.aligned.m16n8k16.row.col.f32.f16.f16.f32 "
        "{%0,%1,%2,%3}, {%4,%5,%6,%7}, {%8,%9}, {%0,%1,%2,%3};"
        : "+f"(c[0]), "+f"(c[1]), "+f"(c[2]), "+f"(c[3])
        : "r"(a[0]), "r"(a[1]), "r"(a[2]), "r"(a[3]), "r"(b[0]), "r"(b[1]));
}
// pack two fp32 -> one fp16x2 (lo = x, hi = y), round-to-nearest
__device__ __forceinline__ uint32_t cvt_f16x2(float2 v) {
    uint32_t r;
    asm("cvt.rn.f16x2.f32 %0, %1, %2;" : "=r"(r) : "f"(v.y), "f"(v.x));
    return r;
}

// ---------------- kernels ----------------

__global__ void gat_prep_w(const float* __restrict__ W) {
    using namespace cfg;
    int idx = blockIdx.x * blockDim.x + threadIdx.x;  // 65536
    int k = idx >> 8, n = idx & 255;
    g_Wh[n * KDIM + k] = __float2half_rn(W[idx]);
}

__global__ __launch_bounds__(cfg::NT, 2)
void gat_mma_gemm(const float* __restrict__ A, float* __restrict__ C) {
    using namespace cfg;
    extern __shared__ char smem[];
    const uint32_t sb = smem_u32(smem);

    const int tid = threadIdx.x;
    const int wid = tid >> 5, lane = tid & 31;
    const int warp_m = wid & 3;        // rows warp_m*32..+31
    const int warp_n = wid >> 2;       // cols warp_n*64..+63
    const size_t rowBase = (size_t)blockIdx.y * BM;
    const int colBase = blockIdx.x * BN;

    // A cp.async: 1024 16B segs per stage, 4 per thread
    const int cpRow = tid >> 3;        // +32*i
    const int cpSeg = tid & 7;
    // W cp.async: 512 16B segs per stage, 2 per thread
    const int wRowLd = tid >> 1;               // 0..127
    const int wSegLd = (tid & 1) * 2;          // segs {0,1} or {2,3}

    auto cp_A = [&](int c) {           // one commit group
        const uint32_t base = sb + OFF_A + (uint32_t)(c % 3) * A_STAGE;
        const float* src = A + (rowBase + cpRow) * KDIM + c * KC + cpSeg * 4;
#pragma unroll
        for (int i = 0; i < 4; i++)
            cp_async16(base + (uint32_t)(cpRow + i * 32) * A_STRIDE_B + cpSeg * 16,
                       src + (size_t)i * 32 * KDIM);
        cp_commit();
    };
    auto cp_W = [&](int c) {           // one commit group
        const uint32_t base = sb + OFF_W + (uint32_t)(c % 3) * W_STAGE
                            + (uint32_t)wRowLd * W_STRIDE_B;
        const __half* src = g_Wh + (size_t)(colBase + wRowLd) * KDIM + c * KC;
#pragma unroll
        for (int i = 0; i < 2; i++)
            cp_async16(base + (wSegLd + i) * 16, src + (wSegLd + i) * 8);
        cp_commit();
    };

    // prologue: groups A0,W0,A1,W1; force A0,W0; A1,W1 may still fly
    cp_A(0); cp_W(0);
    cp_A(1); cp_W(1);
    cp_wait<2>();
    __syncthreads();

    // per-lane fragment address components
    const uint32_t aOff = (uint32_t)(warp_m * 32 + (lane >> 2)) * A_STRIDE_B + (lane & 3) * 8;
    const uint32_t wRow = (uint32_t)(warp_n * 64 + (lane & 15));
    const uint32_t wKo = (uint32_t)((lane >> 4) << 3);  // elems

    float acc[2][8][4];
#pragma unroll
    for (int f = 0; f < 2; f++)
#pragma unroll
        for (int n = 0; n < 8; n++)
#pragma unroll
            for (int q = 0; q < 4; q++) acc[f][n][q] = 0.0f;

#pragma unroll 1
    for (int c = 0; c < NCHUNK; c++) {
        // depth-2 prefetch; stage (c+2)%3 was last read by compute(c-1),
        // which finished before the barrier ending iter c-1.
        if (c + 2 < NCHUNK) { cp_A(c + 2); cp_W(c + 2); }

        const uint32_t aBase = sb + OFF_A + (uint32_t)(c % 3) * A_STAGE + aOff;
        const uint32_t wBase = sb + OFF_W + (uint32_t)(c % 3) * W_STAGE;

#pragma unroll
        for (int s = 0; s < 2; s++) {
            // --- A fragments (two 16x16 tiles): 8 x LDS.64 + 8 x cvt ---
            uint32_t aF[2][4];
#pragma unroll
            for (int f = 0; f < 2; f++) {
                const uint32_t b0 = aBase + (uint32_t)f * (16 * A_STRIDE_B)
                                  + (uint32_t)s * 64;
                aF[f][0] = cvt_f16x2(lds64(b0));
                aF[f][1] = cvt_f16x2(lds64(b0 + 8 * A_STRIDE_B));
                aF[f][2] = cvt_f16x2(lds64(b0 + 32));
                aF[f][3] = cvt_f16x2(lds64(b0 + 8 * A_STRIDE_B + 32));
            }
            // --- W fragments (8 n-tiles, 64 cols): 4 x LDSM.x4 ---
            const uint32_t kcol = (uint32_t)(s * 16) + wKo;
            uint32_t bF[8][2];
#pragma unroll
            for (int p = 0; p < 4; p++) {
                uint32_t r[4];
                ldsm_x4(r, wBase + (wRow + p * 16) * W_STRIDE_B + kcol * 2);
                bF[2 * p][0] = r[0]; bF[2 * p][1] = r[2];
                bF[2 * p + 1][0] = r[1]; bF[2 * p + 1][1] = r[3];
            }
            // --- 16 MMAs ---
#pragma unroll
            for (int f = 0; f < 2; f++)
#pragma unroll
                for (int n = 0; n < 8; n++) mma_f16(acc[f][n], aF[f], bF[n]);
        }

        if (c + 1 < NCHUNK) {
            // ensure groups for chunk c+1 landed; allow the 2 newest to fly
            if (c + 2 < NCHUNK) cp_wait<2>();
            else cp_wait<0>();
            __syncthreads();
        }
    }

    // ---- epilogue: warp -> rows warp_m*32..+31, cols warp_n*64..+63 ----
    const int g = lane >> 2, tg = lane & 3;
#pragma unroll
    for (int f = 0; f < 2; f++) {
        const size_t m0 = rowBase + warp_m * 32 + f * 16 + g;
#pragma unroll
        for (int n = 0; n < 8; n++) {
            const int col = colBase + warp_n * 64 + n * 8 + tg * 2;
            *reinterpret_cast<float2*>(C + m0 * NDIM + col) =
                make_float2(acc[f][n][0], acc[f][n][1]);
            *reinterpret_cast<float2*>(C + (m0 + 8) * NDIM + col) =
                make_float2(acc[f][n][2], acc[f][n][3]);
        }
    }
}

extern "C" void kernel_launch(void* const* d_in, const int* in_sizes, int n_in,
                              void* d_out, int out_size) {
    using namespace cfg;
    const float* A = (const float*)d_in[0];   // inputs [B,T,K] -> [M, 256]
    const float* W = (const float*)d_in[1];   // W [256, 256]
    float* C = (float*)d_out;

    const int M = in_sizes[0] / KDIM;         // 131072

    cudaFuncSetAttribute(gat_mma_gemm, cudaFuncAttributeMaxDynamicSharedMemorySize, SMEM_TOTAL);

    gat_prep_w<<<(KDIM * NDIM) / 256, 256>>>(W);
    dim3 grid(NDIM / BN, M / BM);
    gat_mma_gemm<<<grid, NT, SMEM_TOTAL>>>(A, C);
}

// round 17
// speedup vs baseline: 1.2350x; 1.0571x over previous
#include <cuda_runtime.h>
#include <cuda_fp16.h>
#include <cstdint>

// SimpleGAT reduces exactly to out = inputs @ W (softmax over a broadcast-
// constant axis is uniform; the einsum multiplies H by sum_k(alpha)==1).
// fp32 GEMM M=131072, N=256, K=256 via mma.sync fp16 (base sm_103 target).
// Pure fp16 single-term scheme (calibrated rel_err 2.94e-4 vs 1e-3 gate).
// R16: persistent CTAs (304 = 2/SM), fixed colBase per CTA, W slice loaded
//      ONCE into smem (64KB, XOR-swizzled, no pad) -> per-tile W restreaming
//      (~128MB L2 traffic) eliminated; A pipeline (3-stage, 16KB XOR-swizzled
//      stages) runs continuously ACROSS tiles, removing per-tile prologue
//      stalls and wave transitions. Mainloop fragment math identical to R15.

namespace cfg {
constexpr int KDIM = 256, NDIM = 256;
constexpr int BM = 128, BN = 128, KC = 32;
constexpr int NT = 256;                        // 8 warps (4 M x 2 N)
constexpr int NSM = 152;                       // GB300 SMs
constexpr int NCTA = 2 * NSM;                  // persistent grid
constexpr uint32_t A_STAGE = 128u * 128u;      // 16384 B, swizzled, 3 stages
constexpr uint32_t OFF_W = 3 * A_STAGE;        // 49152
constexpr uint32_t SMEM_TOTAL = OFF_W + 128u * 512u;  // 114688 -> 2 CTAs/SM
}  // namespace cfg

// W transposed to fp16 [n][k].
__device__ __half g_Wh[cfg::NDIM * cfg::KDIM];

// ---------------- helpers ----------------
__device__ __forceinline__ uint32_t smem_u32(const void* p) {
    uint32_t a;
    asm("{ .reg .u64 t; cvta.to.shared.u64 t, %1; cvt.u32.u64 %0, t; }" : "=r"(a) : "l"(p));
    return a;
}
__device__ __forceinline__ void cp_async16(uint32_t dst, const void* src) {
    asm volatile("cp.async.cg.shared.global [%0], [%1], 16;" :: "r"(dst), "l"(src));
}
__device__ __forceinline__ void cp_commit() { asm volatile("cp.async.commit_group;"); }
template <int N>
__device__ __forceinline__ void cp_wait() {
    asm volatile("cp.async.wait_group %0;" :: "n"(N) : "memory");
}
__device__ __forceinline__ void ldsm_x4(uint32_t* r, uint32_t addr) {
    asm volatile("ldmatrix.sync.aligned.m8n8.x4.shared.b16 {%0,%1,%2,%3}, [%4];"
                 : "=r"(r[0]), "=r"(r[1]), "=r"(r[2]), "=r"(r[3]) : "r"(addr));
}
__device__ __forceinline__ float2 lds64(uint32_t addr) {
    float2 v;
    asm volatile("ld.shared.v2.f32 {%0,%1}, [%2];" : "=f"(v.x), "=f"(v.y) : "r"(addr));
    return v;
}
__device__ __forceinline__ void mma_f16(float* c, const uint32_t* a, const uint32_t* b) {
    asm volatile(
        "mma.sync.aligned.m16n8k16.row.col.f32.f16.f16.f32 "
        "{%0,%1,%2,%3}, {%4,%5,%6,%7}, {%8,%9}, {%0,%1,%2,%3};"
        : "+f"(c[0]), "+f"(c[1]), "+f"(c[2]), "+f"(c[3])
        : "r"(a[0]), "r"(a[1]), "r"(a[2]), "r"(a[3]), "r"(b[0]), "r"(b[1]));
}
// pack two fp32 -> one fp16x2 (lo = x, hi = y), round-to-nearest
__device__ __forceinline__ uint32_t cvt_f16x2(float2 v) {
    uint32_t r;
    asm("cvt.rn.f16x2.f32 %0, %1, %2;" : "=r"(r) : "f"(v.y), "f"(v.x));
    return r;
}

// ---------------- kernels ----------------

__global__ void gat_prep_w(const float* __restrict__ W) {
    using namespace cfg;
    int idx = blockIdx.x * blockDim.x + threadIdx.x;  // 65536
    int k = idx >> 8, n = idx & 255;
    g_Wh[n * KDIM + k] = __float2half_rn(W[idx]);
}

__global__ __launch_bounds__(cfg::NT, 2)
void gat_mma_gemm(const float* __restrict__ A, float* __restrict__ C, int mtiles) {
    using namespace cfg;
    extern __shared__ char smem[];
    const uint32_t sb = smem_u32(smem);

    const int tid = threadIdx.x;
    const int wid = tid >> 5, lane = tid & 31;
    const int warp_m = wid & 3;        // rows warp_m*32..+31
    const int warp_n = wid >> 2;       // cols warp_n*64..+63
    const int mSlot = blockIdx.x >> 1;            // 0..151
    const int colBase = (blockIdx.x & 1) * BN;    // fixed per persistent CTA

    // ---- one-shot W slice load: 128 rows x 512B, XOR-swizzled 16B cols ----
    {
        const int n = tid >> 1;
        const int s0 = (tid & 1) * 16;
        const int key = n & 7;
        const uint32_t dbase = sb + OFF_W + (uint32_t)n * 512;
        const __half* src = g_Wh + (size_t)(colBase + n) * KDIM;
#pragma unroll
        for (int i = 0; i < 16; i++) {
            const int seg = s0 + i;
            cp_async16(dbase + (uint32_t)(seg ^ key) * 16, src + seg * 8);
        }
        cp_commit();
    }

    // ---- A chunk loader: rows of 128B, XOR-swizzled 16B segs ----
    const int cpRow = tid >> 3;                 // +32*i
    const int cpSeg = tid & 7;
    const int cpPhys = cpSeg ^ ((cpRow & 3) * 2);
    auto cp_A = [&](int q, int st) {            // q = global chunk index
        const int t = q >> 3, c = q & 7;
        const size_t rowBase = (size_t)(mSlot + t * NSM) * BM;
        const uint32_t base = sb + (uint32_t)st * A_STAGE;
        const float* src = A + (rowBase + cpRow) * KDIM + c * KC + cpSeg * 4;
#pragma unroll
        for (int i = 0; i < 4; i++)
            cp_async16(base + (uint32_t)(cpRow + i * 32) * 128 + cpPhys * 16,
                       src + (size_t)i * 32 * KDIM);
        cp_commit();
    };

    const int ntiles = (mtiles - 1 - mSlot) / NSM + 1;
    const int total = ntiles * 8;

    // prologue: [W][A0][A1]; force W+A0, let A1 fly
    cp_A(0, 0);
    cp_A(1, 1);
    cp_wait<1>();
    __syncthreads();

    // per-lane fragment address components
    const int g = lane >> 2, tg = lane & 3;
    const int akey = (g & 3) << 2;                                   // 8B-word XOR
    const uint32_t aRowOff = (uint32_t)(warp_m * 32 + g) * 128;
    const int wkey = lane & 7;                                       // 16B-col XOR
    const uint32_t wRowBase = sb + OFF_W + (uint32_t)(warp_n * 64 + (lane & 15)) * 512;
    const int c16lane = lane >> 4;

    float acc[2][8][4];
#pragma unroll
    for (int f = 0; f < 2; f++)
#pragma unroll
        for (int n = 0; n < 8; n++)
#pragma unroll
            for (int q = 0; q < 4; q++) acc[f][n][q] = 0.0f;

    int stCur = 0, stP2 = 2;
#pragma unroll 1
    for (int qq = 0; qq < total; qq++) {
        // depth-2 prefetch; stage (qq+2)%3 was last read at qq-1, done before
        // the barrier that ended iteration qq-1.
        if (qq + 2 < total) cp_A(qq + 2, stP2);

        const uint32_t aBase = sb + (uint32_t)stCur * A_STAGE;
        const int c = qq & 7;

#pragma unroll
        for (int s = 0; s < 2; s++) {
            // --- A fragments (two 16x16 tiles): 8 x LDS.64 + 8 x cvt ---
            uint32_t aF[2][4];
            const int w0 = s * 8 + tg;
            const uint32_t o0 = (uint32_t)((w0 ^ akey) << 3);
            const uint32_t o1 = (uint32_t)(((w0 + 4) ^ akey) << 3);
#pragma unroll
            for (int f = 0; f < 2; f++) {
                const uint32_t rb = aBase + aRowOff + (uint32_t)f * 2048;
                aF[f][0] = cvt_f16x2(lds64(rb + o0));
                aF[f][1] = cvt_f16x2(lds64(rb + 1024 + o0));
                aF[f][2] = cvt_f16x2(lds64(rb + o1));
                aF[f][3] = cvt_f16x2(lds64(rb + 1024 + o1));
            }
            // --- W fragments (8 n-tiles): 4 x LDSM.x4 from resident slice ---
            const int c16 = (c * 4 + s * 2) | c16lane;
            const uint32_t wo = (uint32_t)((c16 ^ wkey) << 4);
            uint32_t bF[8][2];
#pragma unroll
            for (int p = 0; p < 4; p++) {
                uint32_t r[4];
                ldsm_x4(r, wRowBase + (uint32_t)p * 8192 + wo);
                bF[2 * p][0] = r[0]; bF[2 * p][1] = r[2];
                bF[2 * p + 1][0] = r[1]; bF[2 * p + 1][1] = r[3];
            }
            // --- 16 MMAs ---
#pragma unroll
            for (int f = 0; f < 2; f++)
#pragma unroll
                for (int n = 0; n < 8; n++) mma_f16(acc[f][n], aF[f], bF[n]);
        }

        // tile boundary: epilogue + acc reset (A prefetch already covers the
        // next tile's first chunks — pipeline never restarts)
        if (c == 7) {
            const size_t rowBase = (size_t)(mSlot + (qq >> 3) * NSM) * BM;
#pragma unroll
            for (int f = 0; f < 2; f++) {
                const size_t m0 = rowBase + warp_m * 32 + f * 16 + g;
#pragma unroll
                for (int n = 0; n < 8; n++) {
                    const int col = colBase + warp_n * 64 + n * 8 + tg * 2;
                    *reinterpret_cast<float2*>(C + m0 * NDIM + col) =
                        make_float2(acc[f][n][0], acc[f][n][1]);
                    *reinterpret_cast<float2*>(C + (m0 + 8) * NDIM + col) =
                        make_float2(acc[f][n][2], acc[f][n][3]);
                    acc[f][n][0] = acc[f][n][1] = acc[f][n][2] = acc[f][n][3] = 0.0f;
                }
            }
        }

        if (qq + 1 < total) {
            if (qq + 2 < total) cp_wait<1>();  // forces A(qq+1); A(qq+2) flies
            else cp_wait<0>();                 // tail
            __syncthreads();
        }
        stCur = (stCur == 2) ? 0 : stCur + 1;
        stP2 = (stP2 == 2) ? 0 : stP2 + 1;
    }
}

extern "C" void kernel_launch(void* const* d_in, const int* in_sizes, int n_in,
                              void* d_out, int out_size) {
    using namespace cfg;
    const float* A = (const float*)d_in[0];   // inputs [B,T,K] -> [M, 256]
    const float* W = (const float*)d_in[1];   // W [256, 256]
    float* C = (float*)d_out;

    const int M = in_sizes[0] / KDIM;         // 131072
    const int mtiles = M / BM;                // 1024

    cudaFuncSetAttribute(gat_mma_gemm, cudaFuncAttributeMaxDynamicSharedMemorySize, SMEM_TOTAL);

    gat_prep_w<<<(KDIM * NDIM) / 256, 256>>>(W);
    gat_mma_gemm<<<NCTA, NT, SMEM_TOTAL>>>(A, C, mtiles);
}